// round 14
// baseline (speedup 1.0000x reference)
#include <cuda_runtime.h>
#include <math.h>

#define NC    19
#define DD    256
#define HW    16384
#define PX    64            // pixels per tile
#define NTILE 2048          // 8*HW/PX
#define NBLK  304           // 2 blocks per SM
#define TPB   256
#define TS    257           // padded tile row stride (floats)
#define GRP   16            // blocks per reduction group
#define NGRP  (NBLK / GRP)  // 19 groups
#define NVEC  (NC * DD / 4) // 1216 float4 per partial array

// -------- device scratch (16B-aligned for float4 access) --------
__device__ __align__(16) float g_PS[NBLK * NC * DD];
__device__ __align__(16) float g_PN[NBLK * NC * DD];
__device__ __align__(16) float g_PC[NBLK * NC];
__device__ __align__(16) float g_L2S[NGRP * NC * DD];
__device__ __align__(16) float g_L2N[NGRP * NC * DD];
__device__ __align__(16) float g_L2C[NGRP * NC];
__device__ unsigned int g_gctr[NGRP];
__device__ unsigned int g_fctr;

// smem words: tile 16448 | accS 4864 | accN 4864 | nhp 512 | cntb 20 |
//             starts 20 | wcnt 38 | pad 2 | ord2 128
#define SMEM_WORDS (PX*TS + 2*NC*DD + 512 + 20 + 20 + 2*NC + 2 + 2*PX)
#define SMEM_BYTES (SMEM_WORDS * 4)

__global__ __launch_bounds__(TPB, 2)
void fse_pass1(const float* __restrict__ in, const int* __restrict__ tgt,
               float* __restrict__ out)
{
    extern __shared__ __align__(16) float sm[];
    float* tile   = sm;
    float* accS   = tile + PX * TS;
    float* accN   = accS + NC * DD;
    float* nhp    = accN + NC * DD;
    float* cntb   = nhp + 512;
    int*   starts = (int*)(cntb + 20);
    int*   wcnt   = starts + 20;
    int2*  ord2   = (int2*)(wcnt + 38 + 2);
    __shared__ int s_role;

    const int tid  = threadIdx.x;
    const int lane = tid & 31;
    const int wrp  = tid >> 5;
    const int hi   = lane >> 4;
    const int px0  = (lane & 15) << 2;

    for (int i = tid; i < NC * DD; i += TPB) { accS[i] = 0.f; accN[i] = 0.f; }
    if (tid < NC) cntb[tid] = 0.f;
    __syncthreads();

    for (int t = blockIdx.x; t < NTILE; t += NBLK) {
        __syncthreads();
        const int b   = t >> 8;
        const int hw0 = (t & 255) << 6;
        const float* src = in + (size_t)b * DD * HW + hw0;

        int myLab = 0;
        if (tid < PX) myLab = tgt[b * HW + hw0 + tid];
        if (tid >= 64 && tid < 64 + 2 * NC) wcnt[tid - 64] = 0;

        // ---- stage via LDG.128 + fused norm partials ----
        {
            float s0 = 0.f, s1 = 0.f, s2 = 0.f, s3 = 0.f;
            #pragma unroll
            for (int it = 0; it < 16; ++it) {
                const int d = (wrp << 5) + (it << 1) + hi;
                const float4 v = *(const float4*)(src + (size_t)d * HW + px0);
                float* tb = tile + d;
                tb[(px0    ) * TS] = v.x;
                tb[(px0 + 1) * TS] = v.y;
                tb[(px0 + 2) * TS] = v.z;
                tb[(px0 + 3) * TS] = v.w;
                s0 += v.x * v.x; s1 += v.y * v.y; s2 += v.z * v.z; s3 += v.w * v.w;
            }
            s0 += __shfl_xor_sync(0xffffffffu, s0, 16);
            s1 += __shfl_xor_sync(0xffffffffu, s1, 16);
            s2 += __shfl_xor_sync(0xffffffffu, s2, 16);
            s3 += __shfl_xor_sync(0xffffffffu, s3, 16);
            if (hi == 0)
                *(float4*)(nhp + (wrp << 6) + px0) = make_float4(s0, s1, s2, s3);
        }
        __syncthreads();

        // ---- ballot ranks + per-warp class histogram + rinv ----
        int   myRank = 0;
        float myR    = 0.f;
        if (tid < PX) {
            unsigned m  = __match_any_sync(0xffffffffu, myLab);
            unsigned lt = m & ((1u << lane) - 1u);
            myRank = __popc(lt);
            if (lt == 0u) wcnt[wrp * NC + myLab] = __popc(m);
            float n2 = 0.f;
            #pragma unroll
            for (int k = 0; k < 8; ++k) n2 += nhp[(k << 6) + tid];
            myR = rsqrtf(n2);
        }
        __syncthreads();

        // ---- warp-0 shfl prefix scan ----
        if (wrp == 0) {
            int ct = (lane < NC) ? (wcnt[lane] + wcnt[NC + lane]) : 0;
            int incl = ct;
            #pragma unroll
            for (int o = 1; o < 32; o <<= 1) {
                const int nb = __shfl_up_sync(0xffffffffu, incl, o);
                if (lane >= o) incl += nb;
            }
            if (lane < NC) { starts[lane] = incl - ct; cntb[lane] += (float)ct; }
        }
        __syncthreads();

        // ---- scatter class-sorted order ----
        if (tid < PX) {
            const int woff = (wrp > 0) ? wcnt[myLab] : 0;
            ord2[starts[myLab] + woff + myRank] =
                make_int2(tid | (myLab << 8), __float_as_int(myR));
        }
        __syncthreads();

        // ---- accumulate: flat 64-entry walk, run-length flush ----
        {
            int ccur = -1; float sS = 0.f, sN = 0.f;
            #pragma unroll 4
            for (int k = 0; k < PX; ++k) {
                const int2 e = ord2[k];
                const int   p   = e.x & 255;
                const int   cls = e.x >> 8;
                const float r   = __int_as_float(e.y);
                const float v   = tile[p * TS + tid];
                if (cls != ccur) {
                    if (ccur >= 0) { accS[ccur * DD + tid] += sS; accN[ccur * DD + tid] += sN; }
                    ccur = cls; sS = 0.f; sN = 0.f;
                }
                sS += v; sN += v * r;
            }
            accS[ccur * DD + tid] += sS; accN[ccur * DD + tid] += sN;
        }
    }
    __syncthreads();

    // ---- flush per-block partials ----
    {
        const float4* aS4 = (const float4*)accS;
        const float4* aN4 = (const float4*)accN;
        float4* pS4 = (float4*)(g_PS + (size_t)blockIdx.x * NC * DD);
        float4* pN4 = (float4*)(g_PN + (size_t)blockIdx.x * NC * DD);
        for (int i = tid; i < NVEC; i += TPB) {
            pS4[i] = aS4[i];
            pN4[i] = aN4[i];
        }
    }
    if (tid < NC) g_PC[blockIdx.x * NC + tid] = cntb[tid];
    __threadfence();
    __syncthreads();

    // ================= level-1: last block per group reduces its 16 =================
    const int grp = blockIdx.x / GRP;
    if (tid == 0) s_role = (atomicAdd(&g_gctr[grp], 1u) == GRP - 1) ? 1 : 0;
    __syncthreads();
    if (!s_role) return;
    __threadfence();                             // acquire

    {
        const float4* pS = (const float4*)g_PS + (size_t)grp * GRP * NVEC;
        const float4* pN = (const float4*)g_PN + (size_t)grp * GRP * NVEC;
        float4* lS = (float4*)g_L2S + (size_t)grp * NVEC;
        float4* lN = (float4*)g_L2N + (size_t)grp * NVEC;
        for (int v = tid; v < NVEC; v += TPB) {
            float4 aS = make_float4(0.f, 0.f, 0.f, 0.f);
            float4 aN = make_float4(0.f, 0.f, 0.f, 0.f);
            #pragma unroll 4
            for (int b = 0; b < GRP; ++b) {      // fixed order (deterministic)
                const float4 wS = __ldcg(pS + (size_t)b * NVEC + v);
                const float4 wN = __ldcg(pN + (size_t)b * NVEC + v);
                aS.x += wS.x; aS.y += wS.y; aS.z += wS.z; aS.w += wS.w;
                aN.x += wN.x; aN.y += wN.y; aN.z += wN.z; aN.w += wN.w;
            }
            lS[v] = aS;
            lN[v] = aN;
        }
        if (tid < NC) {
            float c = 0.f;
            #pragma unroll
            for (int b = 0; b < GRP; ++b) c += __ldcg(&g_PC[(grp * GRP + b) * NC + tid]);
            g_L2C[grp * NC + tid] = c;
        }
    }
    __threadfence();
    __syncthreads();

    // ================= level-2: last group computes the loss =================
    if (tid == 0) s_role = (atomicAdd(&g_fctr, 1u) == NGRP - 1) ? 2 : 0;
    __syncthreads();
    if (s_role != 2) return;
    __threadfence();                             // acquire

    // reuse dynamic smem for the epilogue
    float* cen   = sm;                           // NC*DD
    float* nsm   = sm + NC * DD;                 // NC*DD
    float* cnt_s = nsm + NC * DD;                // NC
    float* ncn   = cnt_s + 32;
    float* nsd   = ncn + 32;
    float* pl    = nsd + 32;
    float* pp    = pl + 32;                      // NC*NC
    __syncthreads();                             // everyone past role check before smem reuse

    if (tid < NC) {
        float c = 0.f;
        #pragma unroll
        for (int g = 0; g < NGRP; ++g) c += __ldcg(&g_L2C[g * NC + tid]);
        cnt_s[tid] = c;
    }
    __syncthreads();

    for (int v = tid; v < NVEC; v += TPB) {
        float4 sS = make_float4(0.f, 0.f, 0.f, 0.f);
        float4 sN = make_float4(0.f, 0.f, 0.f, 0.f);
        #pragma unroll 4
        for (int g = 0; g < NGRP; ++g) {         // fixed order
            const float4 wS = __ldcg((const float4*)g_L2S + (size_t)g * NVEC + v);
            const float4 wN = __ldcg((const float4*)g_L2N + (size_t)g * NVEC + v);
            sS.x += wS.x; sS.y += wS.y; sS.z += wS.z; sS.w += wS.w;
            sN.x += wN.x; sN.y += wN.y; sN.z += wN.z; sN.w += wN.w;
        }
        const float c = fmaxf(cnt_s[(4 * v) >> 8], 1.f);
        ((float4*)nsm)[v] = sN;
        ((float4*)cen)[v] = make_float4(sS.x / c, sS.y / c, sS.z / c, sS.w / c);
    }
    __syncthreads();

    // per-class norm + dot(center, nsum): warp per class, lanes over d
    for (int c = wrp; c < NC; c += 8) {
        float n2 = 0.f, dt = 0.f;
        #pragma unroll
        for (int k = 0; k < 8; ++k) {
            const int d = lane + (k << 5);
            const float cv = cen[c * DD + d];
            n2 += cv * cv;
            dt += cv * nsm[c * DD + d];
        }
        #pragma unroll
        for (int o = 16; o; o >>= 1) {
            n2 += __shfl_down_sync(0xffffffffu, n2, o);
            dt += __shfl_down_sync(0xffffffffu, dt, o);
        }
        if (lane == 0) { ncn[c] = sqrtf(n2); nsd[c] = dt; }
    }
    __syncthreads();

    // Gram matrix: warp per pair, lanes over d (conflict-free)
    for (int pr = wrp; pr < NC * NC; pr += 8) {
        const int i = pr / NC, j = pr - i * NC;
        float g = 0.f;
        #pragma unroll
        for (int k = 0; k < 8; ++k) {
            const int d = lane + (k << 5);
            g += cen[i * DD + d] * cen[j * DD + d];
        }
        #pragma unroll
        for (int o = 16; o; o >>= 1) g += __shfl_down_sync(0xffffffffu, g, o);
        if (lane == 0) {
            const float S = g / fmaxf(ncn[i] * ncn[j], 1e-8f);
            pp[pr] = (i == j) ? (1.f - S) : fmaxf(S, 0.f);
        }
    }
    __syncthreads();
    if (tid < NC) {
        float vv = 0.f;
        if (cnt_s[tid] > 0.f) {
            float m = 0.f;
            for (int j = 0; j < NC; ++j) m += pp[tid * NC + j];
            vv = m / (float)NC + 1.f - nsd[tid] / (ncn[tid] * cnt_s[tid]);
        }
        pl[tid] = vv;
    }
    __syncthreads();
    if (tid == 0) {
        float tot = 0.f;
        for (int i = 0; i < NC; ++i) tot += pl[i];
        out[0] = tot;
        g_fctr = 0;                              // reset for graph replay
    }
    if (tid < NGRP) g_gctr[tid] = 0;             // reset for graph replay
}

extern "C" void kernel_launch(void* const* d_in, const int* in_sizes, int n_in,
                              void* d_out, int out_size)
{
    const float* in  = (const float*)d_in[0];
    const int*   tgt = (const int*)d_in[1];
    float*       out = (float*)d_out;

    cudaFuncSetAttribute(fse_pass1, cudaFuncAttributeMaxDynamicSharedMemorySize, SMEM_BYTES);
    fse_pass1<<<NBLK, TPB, SMEM_BYTES>>>(in, tgt, out);
}